// round 6
// baseline (speedup 1.0000x reference)
#include <cuda_runtime.h>
#include <math.h>

#define NCELL 16
#define CH    256

// Tables: per (cell m, channel c):
//  g_psi[m*CH+c] = (E, F) with closed-form step  p' = E*p + F
//  g_eul[m*CH+c] = (EA,EB) with Euler substep    p' = EA*p + EB
__device__ float2 g_psi[NCELL * CH];
__device__ float2 g_eul[NCELL * CH];

// ---------------------------------------------------------------------------
// Setup: reproduce np.linalg.svd(L) null-space rows (LAPACK dgesdd Path 4t:
// rows 17..31 of VT are rows 17..31 of Q = H(17)...H(1) from the LQ of L),
// then build the per-(cell,channel) affine-step tables, and copy theta to the
// output tail.
// ---------------------------------------------------------------------------
__global__ void cpab_setup(const float* __restrict__ theta,
                           const void*  __restrict__ timep,
                           float* __restrict__ out_tail, int tail_n)
{
    __shared__ double Ad[17][32];   // L, overwritten by LQ factors
    __shared__ double Qd[32][32];   // accumulated Q
    __shared__ double tau[17];
    __shared__ float  Bf[32][15];   // basis (float32, matching reference cast)
    __shared__ float  s_dt[2];

    const int tid = threadIdx.x;

    // Build L (fp64)
    for (int i = tid; i < 17 * 32; i += 256) ((double*)Ad)[i] = 0.0;
    __syncthreads();
    if (tid == 0) {
        for (int k = 1; k < NCELL; k++) {
            double xk = (double)k / (double)NCELL;
            Ad[k - 1][2 * (k - 1)]     =  xk;
            Ad[k - 1][2 * (k - 1) + 1] =  1.0;
            Ad[k - 1][2 * k]           = -xk;
            Ad[k - 1][2 * k + 1]       = -1.0;
        }
        Ad[NCELL - 1][1]          = 1.0;
        Ad[NCELL][2 * NCELL - 2]  = 1.0;
        Ad[NCELL][2 * NCELL - 1]  = 1.0;

        // time scalar: robust to int32/int64/float32 storage (value is 1)
        int   iv = *(const int*)timep;
        float fv = *(const float*)timep;
        float t;
        if (iv > 0 && iv < 1000000)            t = (float)iv;
        else if (fv > 0.0f && fv < 1.0e6f)     t = fv;
        else                                   t = 1.0f;
        float dt = t / 10.0f;          // NSTEPS1 = 10
        s_dt[0] = dt;
        s_dt[1] = dt / 5.0f;           // NSTEPS2 = 5
    }
    __syncthreads();

    // --- LQ factorization with LAPACK dlarfg sign convention ---
    for (int i = 0; i < 17; i++) {
        if (tid == 0) {
            double s0 = 0.0, s1 = 0.0, s2 = 0.0, s3 = 0.0;
            for (int j = i + 1; j < 32; j += 4) {
                s0 += Ad[i][j] * Ad[i][j];
                if (j + 1 < 32) s1 += Ad[i][j + 1] * Ad[i][j + 1];
                if (j + 2 < 32) s2 += Ad[i][j + 2] * Ad[i][j + 2];
                if (j + 3 < 32) s3 += Ad[i][j + 3] * Ad[i][j + 3];
            }
            double xn2 = (s0 + s1) + (s2 + s3);
            double alpha = Ad[i][i];
            if (xn2 == 0.0) {
                tau[i] = 0.0;
            } else {
                double r    = sqrt(alpha * alpha + xn2);
                double beta = (alpha >= 0.0) ? -r : r;
                tau[i] = (beta - alpha) / beta;
                double sc = 1.0 / (alpha - beta);
                for (int j = i + 1; j < 32; j++) Ad[i][j] *= sc;
                Ad[i][i] = beta;
            }
        }
        __syncthreads();
        double ti = tau[i];
        if (ti != 0.0 && tid > i && tid < 17) {
            int rr = tid;
            double w0 = Ad[rr][i], w1 = 0.0, w2 = 0.0, w3 = 0.0;
            for (int j = i + 1; j < 32; j += 4) {
                w0 += Ad[rr][j] * Ad[i][j];
                if (j + 1 < 32) w1 += Ad[rr][j + 1] * Ad[i][j + 1];
                if (j + 2 < 32) w2 += Ad[rr][j + 2] * Ad[i][j + 2];
                if (j + 3 < 32) w3 += Ad[rr][j + 3] * Ad[i][j + 3];
            }
            double w = ((w0 + w1) + (w2 + w3)) * ti;
            Ad[rr][i] -= w;
            for (int j = i + 1; j < 32; j++) Ad[rr][j] -= w * Ad[i][j];
        }
        __syncthreads();
    }

    // --- Q = H(17)...H(1): M := H(i)*M for i ascending, M starts as I ---
    for (int i = tid; i < 32 * 32; i += 256) ((double*)Qd)[i] = (i % 33 == 0) ? 1.0 : 0.0;
    __syncthreads();
    for (int i = 0; i < 17; i++) {
        double ti = tau[i];
        if (ti != 0.0 && tid < 32) {
            int jc = tid;
            double s0 = Qd[i][jc], s1 = 0.0, s2 = 0.0, s3 = 0.0;
            for (int j = i + 1; j < 32; j += 4) {
                s0 += Ad[i][j] * Qd[j][jc];
                if (j + 1 < 32) s1 += Ad[i][j + 1] * Qd[j + 1][jc];
                if (j + 2 < 32) s2 += Ad[i][j + 2] * Qd[j + 2][jc];
                if (j + 3 < 32) s3 += Ad[i][j + 3] * Qd[j + 3][jc];
            }
            double s = ((s0 + s1) + (s2 + s3)) * ti;
            Qd[i][jc] -= s;
            for (int j = i + 1; j < 32; j++) Qd[j][jc] -= Ad[i][j] * s;
        }
        __syncthreads();
    }

    // B_BASIS[k][j] = VT[17+j][k] = Qd[17+j][k], cast to float32
    for (int idx = tid; idx < 32 * 15; idx += 256) {
        int k = idx / 15, j = idx % 15;
        Bf[k][j] = (float)Qd[17 + j][k];
    }
    __syncthreads();

    // --- per-channel tables (fp32, matching reference theta @ B^T in f32) ---
    {
        const int c = tid;                 // 256 channels, 256 threads
        const float dt = s_dt[0], ddt = s_dt[1];
        float th[15];
        #pragma unroll
        for (int j = 0; j < 15; j++) th[j] = theta[c * 15 + j];

        #pragma unroll
        for (int m = 0; m < NCELL; m++) {
            float af = 0.0f, bf = 0.0f;
            #pragma unroll
            for (int j = 0; j < 15; j++) {
                af = fmaf(th[j], Bf[2 * m][j],     af);
                bf = fmaf(th[j], Bf[2 * m + 1][j], bf);
            }
            float E, F;
            if (fabsf(af) > 1e-7f) {
                float eta = expf(dt * af);
                E = eta;
                F = bf / af * (eta - 1.0f);
            } else {
                E = 1.0f;
                F = bf * dt;
            }
            g_psi[m * CH + c] = make_float2(E, F);
            g_eul[m * CH + c] = make_float2(fmaf(ddt, af, 1.0f), ddt * bf);
        }
    }

    // theta passthrough into output tail
    for (int j = tid; j < tail_n; j += 256) out_tail[j] = theta[j];
}

// ---------------------------------------------------------------------------
// Main transform: out[n,c] = f_c(x[n,c]) — the sort in the reference is a
// no-op (all ops elementwise). 2 rows per thread-iteration for ILP.
// ---------------------------------------------------------------------------
__device__ __forceinline__ int cell_of(float p)
{
    int c = __float2int_rd(p * 16.0f);
    return min(15, max(0, c));
}

__device__ __forceinline__ void step_one(float& q, int ch,
                                         const float2* __restrict__ s_psi,
                                         const float2* __restrict__ s_eul)
{
    int c0 = cell_of(q);
    float2 ef = s_psi[(c0 << 8) + ch];
    float pc = fmaf(ef.x, q, ef.y);
    if (cell_of(pc) == c0) {
        q = pc;
    } else {
        #pragma unroll
        for (int t = 0; t < 5; t++) {
            int cc = cell_of(q);
            float2 ab = s_eul[(cc << 8) + ch];
            q = fmaf(ab.x, q, ab.y);
        }
    }
}

__global__ __launch_bounds__(CH) void cpab_main(const float* __restrict__ x,
                                                float* __restrict__ out,
                                                int Nrows)
{
    extern __shared__ float2 smem[];
    float2* s_psi = smem;
    float2* s_eul = smem + NCELL * CH;

    const int tid = threadIdx.x;   // == channel
    for (int i = tid; i < NCELL * CH; i += CH) {
        s_psi[i] = g_psi[i];
        s_eul[i] = g_eul[i];
    }
    __syncthreads();

    for (int r0 = blockIdx.x * 2; r0 < Nrows; r0 += gridDim.x * 2) {
        int r1 = r0 + 1;
        bool has1 = (r1 < Nrows);

        float xv0 = x[(size_t)r0 * CH + tid];
        float xv1 = has1 ? x[(size_t)r1 * CH + tid] : 0.0f;

        float p0 = (xv0 + 3.0f) / 6.0f;
        float p1 = (xv1 + 3.0f) / 6.0f;
        bool ood0 = (p0 >= 1.0f) || (p0 <= 0.0f);
        bool ood1 = (p1 >= 1.0f) || (p1 <= 0.0f);

        float q0 = p0, q1 = p1;
        #pragma unroll 1
        for (int s = 0; s < 10; s++) {
            step_one(q0, tid, s_psi, s_eul);
            step_one(q1, tid, s_psi, s_eul);
        }

        out[(size_t)r0 * CH + tid] = ood0 ? xv0 : fmaf(q0, 6.0f, -3.0f);
        if (has1)
            out[(size_t)r1 * CH + tid] = ood1 ? xv1 : fmaf(q1, 6.0f, -3.0f);
    }
}

// ---------------------------------------------------------------------------
extern "C" void kernel_launch(void* const* d_in, const int* in_sizes, int n_in,
                              void* d_out, int out_size)
{
    const float* x     = (const float*)d_in[0];
    const void*  timep = d_in[4];
    const float* theta = (const float*)d_in[5];
    const int xsz  = in_sizes[0];                 // N * 256
    const int thsz = in_sizes[5];                 // 256 * 15
    const int Nrows = xsz / CH;
    float* out = (float*)d_out;

    cpab_setup<<<1, 256>>>(theta, timep, out + xsz, thsz);

    const int smem_bytes = 2 * NCELL * CH * (int)sizeof(float2);   // 64 KB
    cudaFuncSetAttribute(cpab_main, cudaFuncAttributeMaxDynamicSharedMemorySize,
                         smem_bytes);

    int pairs = (Nrows + 1) / 2;
    int grid  = pairs < 1776 ? pairs : 1776;      // 148 SMs * 3 blocks * 4 waves
    cpab_main<<<grid, CH, smem_bytes>>>(x, out, Nrows);
}

// round 8
// speedup vs baseline: 2.0173x; 2.0173x over previous
#include <cuda_runtime.h>
#include <math.h>

#define NCELL 16
#define CH    256

struct Basis { float B[32 * 15]; };   // B[k*15+j] = B_BASIS[k][j] (fp32)

// Tables: per (cell m, channel c):
//  g_psi[m*CH+c] = (E, F)  closed-form step  p' = E*p + F
//  g_eul[m*CH+c] = (EA,EB) Euler substep     p' = EA*p + EB
__device__ float2 g_psi[NCELL * CH];
__device__ float2 g_eul[NCELL * CH];

// ---------------------------------------------------------------------------
// Host: reproduce np.linalg.svd(L) null-space rows. LAPACK dgesdd Path 4t
// (M=17 < N=32, N >= MNTHR): rows 17..31 of VT are rows 17..31 of
// Q = H(17)...H(1) from the LQ factorization of L. Pure fp64 arithmetic,
// deterministic, depends only on compile-time constants -> host-side OK.
// ---------------------------------------------------------------------------
static void compute_basis_host(Basis* out)
{
    double Ad[17][32];
    double Qd[32][32];
    double tau[17];

    for (int i = 0; i < 17; i++)
        for (int j = 0; j < 32; j++) Ad[i][j] = 0.0;

    for (int k = 1; k < NCELL; k++) {
        double xk = (double)k / (double)NCELL;
        Ad[k - 1][2 * (k - 1)]     =  xk;
        Ad[k - 1][2 * (k - 1) + 1] =  1.0;
        Ad[k - 1][2 * k]           = -xk;
        Ad[k - 1][2 * k + 1]       = -1.0;
    }
    Ad[NCELL - 1][1]         = 1.0;
    Ad[NCELL][2 * NCELL - 2] = 1.0;
    Ad[NCELL][2 * NCELL - 1] = 1.0;

    // LQ with LAPACK dlarfg sign convention
    for (int i = 0; i < 17; i++) {
        double xn2 = 0.0;
        for (int j = i + 1; j < 32; j++) xn2 += Ad[i][j] * Ad[i][j];
        double alpha = Ad[i][i];
        if (xn2 == 0.0) {
            tau[i] = 0.0;
        } else {
            double r    = sqrt(alpha * alpha + xn2);
            double beta = (alpha >= 0.0) ? -r : r;
            tau[i] = (beta - alpha) / beta;
            double sc = 1.0 / (alpha - beta);
            for (int j = i + 1; j < 32; j++) Ad[i][j] *= sc;
            Ad[i][i] = beta;
        }
        double ti = tau[i];
        if (ti != 0.0) {
            for (int rr = i + 1; rr < 17; rr++) {
                double w = Ad[rr][i];
                for (int j = i + 1; j < 32; j++) w += Ad[rr][j] * Ad[i][j];
                w *= ti;
                Ad[rr][i] -= w;
                for (int j = i + 1; j < 32; j++) Ad[rr][j] -= w * Ad[i][j];
            }
        }
    }

    // Q = H(17)...H(1), applied to I (M := H(i)*M, i ascending)
    for (int i = 0; i < 32; i++)
        for (int j = 0; j < 32; j++) Qd[i][j] = (i == j) ? 1.0 : 0.0;

    for (int i = 0; i < 17; i++) {
        double ti = tau[i];
        if (ti == 0.0) continue;
        for (int jc = 0; jc < 32; jc++) {
            double s = Qd[i][jc];
            for (int j = i + 1; j < 32; j++) s += Ad[i][j] * Qd[j][jc];
            s *= ti;
            Qd[i][jc] -= s;
            for (int j = i + 1; j < 32; j++) Qd[j][jc] -= Ad[i][j] * s;
        }
    }

    // B_BASIS[k][j] = VT[17+j][k] = Qd[17+j][k], cast to fp32
    for (int k = 0; k < 32; k++)
        for (int j = 0; j < 15; j++)
            out->B[k * 15 + j] = (float)Qd[17 + j][k];
}

// ---------------------------------------------------------------------------
// Tiny setup kernel: per-(cell,channel) affine tables + theta passthrough.
// ---------------------------------------------------------------------------
__global__ void cpab_setup(const float* __restrict__ theta,
                           const void*  __restrict__ timep,
                           float* __restrict__ out_tail, int tail_n,
                           Basis bb)
{
    const int c = threadIdx.x;     // channel

    // time scalar: robust to int32/int64/float32 storage (value is 1)
    int   iv = *(const int*)timep;
    float fv = *(const float*)timep;
    float t;
    if (iv > 0 && iv < 1000000)        t = (float)iv;
    else if (fv > 0.0f && fv < 1.0e6f) t = fv;
    else                               t = 1.0f;
    float dt  = t / 10.0f;     // NSTEPS1 = 10
    float ddt = dt / 5.0f;     // NSTEPS2 = 5

    float th[15];
    #pragma unroll
    for (int j = 0; j < 15; j++) th[j] = theta[c * 15 + j];

    #pragma unroll
    for (int m = 0; m < NCELL; m++) {
        float af = 0.0f, bf = 0.0f;
        #pragma unroll
        for (int j = 0; j < 15; j++) {
            af = fmaf(th[j], bb.B[(2 * m) * 15 + j],     af);
            bf = fmaf(th[j], bb.B[(2 * m + 1) * 15 + j], bf);
        }
        float E, F;
        if (fabsf(af) > 1e-7f) {
            float eta = expf(dt * af);
            E = eta;
            F = bf / af * (eta - 1.0f);
        } else {
            E = 1.0f;
            F = bf * dt;
        }
        g_psi[m * CH + c] = make_float2(E, F);
        g_eul[m * CH + c] = make_float2(fmaf(ddt, af, 1.0f), ddt * bf);
    }

    for (int j = c; j < tail_n; j += 256) out_tail[j] = theta[j];
}

// ---------------------------------------------------------------------------
// Main transform. Cell computation replicates the reference exactly:
// t = q*16 rounded-to-nearest (FMUL), then floor, done via the fp bias trick
// (FADD.RD of 1.5*2^23 -> low mantissa bits == floor(t) for t in [0, 2^22)).
// Stay check = raw integer compare of biased bits (no clamp needed for
// in-range lanes; out-of-range lanes are discarded by the ood mask, their
// table index is only kept memory-safe via the unsigned min).
// ---------------------------------------------------------------------------
#define FBIAS 12582912.0f   // 1.5 * 2^23

__device__ __forceinline__ int fcell_bits(float q)
{
    float t = q * 16.0f;              // RN, matches reference x*NC
    return __float_as_int(__fadd_rd(t, FBIAS));   // low bits = floor(t)
}

__device__ __forceinline__ int cix(int bits)
{
    unsigned u = (unsigned)(bits & 63);
    return (int)min(u, 15u);          // memory-safe clamp [0,15]
}

__global__ __launch_bounds__(1024, 2)
void cpab_main(const float* __restrict__ x, float* __restrict__ out, int Nrows)
{
    extern __shared__ float2 smem[];
    float2* s_psi = smem;
    float2* s_eul = smem + NCELL * CH;

    const int tid = threadIdx.x;
    for (int i = tid; i < NCELL * CH; i += 1024) {
        s_psi[i] = g_psi[i];
        s_eul[i] = g_eul[i];
    }
    __syncthreads();

    const int ch = tid & 255;          // channel
    const int g  = tid >> 8;           // row group 0..3

    for (int r0 = blockIdx.x * 8 + g * 2; r0 < Nrows; r0 += gridDim.x * 8) {
        const int  r1   = r0 + 1;
        const bool has1 = (r1 < Nrows);

        float xv0 = x[(size_t)r0 * CH + ch];
        float xv1 = has1 ? x[(size_t)r1 * CH + ch] : 0.0f;

        float p0 = (xv0 + 3.0f) / 6.0f;
        float p1 = (xv1 + 3.0f) / 6.0f;
        bool ood0 = (p0 >= 1.0f) || (p0 <= 0.0f);
        bool ood1 = (p1 >= 1.0f) || (p1 <= 0.0f);

        float q0 = p0, q1 = p1;

        #pragma unroll 1
        for (int s = 0; s < 10; s++) {
            int b0 = fcell_bits(q0);
            int b1 = fcell_bits(q1);
            float2 ef0 = s_psi[(cix(b0) << 8) + ch];
            float2 ef1 = s_psi[(cix(b1) << 8) + ch];
            float pc0 = fmaf(ef0.x, q0, ef0.y);
            float pc1 = fmaf(ef1.x, q1, ef1.y);
            bool st0 = (fcell_bits(pc0) == b0);
            bool st1 = (fcell_bits(pc1) == b1);
            if (st0 & st1) {
                q0 = pc0;
                q1 = pc1;
            } else {
                float e0 = q0, e1 = q1;
                #pragma unroll
                for (int u = 0; u < 5; u++) {
                    float2 a0 = s_eul[(cix(fcell_bits(e0)) << 8) + ch];
                    float2 a1 = s_eul[(cix(fcell_bits(e1)) << 8) + ch];
                    e0 = fmaf(a0.x, e0, a0.y);
                    e1 = fmaf(a1.x, e1, a1.y);
                }
                q0 = st0 ? pc0 : e0;
                q1 = st1 ? pc1 : e1;
            }
        }

        out[(size_t)r0 * CH + ch] = ood0 ? xv0 : fmaf(q0, 6.0f, -3.0f);
        if (has1)
            out[(size_t)r1 * CH + ch] = ood1 ? xv1 : fmaf(q1, 6.0f, -3.0f);
    }
}

// ---------------------------------------------------------------------------
extern "C" void kernel_launch(void* const* d_in, const int* in_sizes, int n_in,
                              void* d_out, int out_size)
{
    const float* x     = (const float*)d_in[0];
    const void*  timep = d_in[4];
    const float* theta = (const float*)d_in[5];
    const int xsz  = in_sizes[0];                 // N * 256
    const int thsz = in_sizes[5];                 // 256 * 15
    const int Nrows = xsz / CH;
    float* out = (float*)d_out;

    Basis bb;
    compute_basis_host(&bb);                      // pure host arithmetic

    cpab_setup<<<1, 256>>>(theta, timep, out + xsz, thsz, bb);

    const int smem_bytes = 2 * NCELL * CH * (int)sizeof(float2);   // 64 KB
    cudaFuncSetAttribute(cpab_main, cudaFuncAttributeMaxDynamicSharedMemorySize,
                         smem_bytes);

    int maxblocks = (Nrows + 7) / 8;
    int grid = 296 < maxblocks ? 296 : maxblocks;  // 148 SMs * 2 blocks
    cpab_main<<<grid, 1024, smem_bytes>>>(x, out, Nrows);
}